// round 11
// baseline (speedup 1.0000x reference)
#include <cuda_runtime.h>
#include <cuda_fp16.h>
#include <cstdint>
#include <cfloat>

#define BB 32
#define TT 16384
#define TP 16416
#define KW 21
#define TCV (TT - KW + 1)   /* 16364 */

// smem: A-hi[148x128B] | A-lo | B[2 bufs][2 taps x 16K]
#define OFF_AH 0
#define OFF_AL 18944
#define OFF_B  37888
#define SMEM_TOTAL 103424

// ---------------- device scratch ----------------
__device__ __align__(16) __half g_xh[BB * TP * 64];
__device__ __align__(16) __half g_xl[BB * TP * 64];
__device__ __align__(16) __half g_wh[KW * 128 * 64];
__device__ __align__(16) float g_y2[(size_t)BB * 64 * TT];   /* conv2 raw [b][c][t] */
__device__ float g_bs[256 * 4096];                           /* stats partials [slot][cta] */
__device__ float g_part[32 * 64 * 3 * 128];                  /* max partials [b][c][w][tile] */
__device__ double g_sumd[128];
__device__ double g_sqd[128];
__device__ float g_feat[BB * 384];

// ---------------- asm helpers (sm_80-portable) ----------------
__device__ __forceinline__ uint32_t smem_u32(const void* p) {
    uint32_t r;
    asm("{ .reg .u64 t; cvta.to.shared.u64 t, %1; cvt.u32.u64 %0, t; }" : "=r"(r) : "l"(p));
    return r;
}
__device__ __forceinline__ void cp16(uint32_t d, const void* s) {
    asm volatile("cp.async.cg.shared.global [%0], [%1], 16;" :: "r"(d), "l"(s));
}
#define CP_COMMIT asm volatile("cp.async.commit_group;" ::: "memory")
#define CP_WAIT1  asm volatile("cp.async.wait_group 1;" ::: "memory")
#define CP_WAIT0  asm volatile("cp.async.wait_group 0;" ::: "memory")

__device__ __forceinline__ void ldsm4(uint32_t* r, uint32_t a) {
    asm volatile("ldmatrix.sync.aligned.m8n8.x4.shared.b16 {%0,%1,%2,%3}, [%4];"
        : "=r"(r[0]), "=r"(r[1]), "=r"(r[2]), "=r"(r[3]) : "r"(a));
}
// f32-accumulate HMMA (main pass)
#define MMA16816(D, A, B0, B1) asm volatile( \
    "mma.sync.aligned.m16n8k16.row.col.f32.f16.f16.f32 " \
    "{%0,%1,%2,%3}, {%4,%5,%6,%7}, {%8,%9}, {%0,%1,%2,%3};" \
    : "+f"((D)[0]), "+f"((D)[1]), "+f"((D)[2]), "+f"((D)[3]) \
    : "r"((A)[0]), "r"((A)[1]), "r"((A)[2]), "r"((A)[3]), "r"(B0), "r"(B1))
// f16-accumulate HMMA (lo-correction pass; result magnitude ~2^-11)
#define MMAH16816(D, A, B0, B1) asm volatile( \
    "mma.sync.aligned.m16n8k16.row.col.f16.f16.f16.f16 " \
    "{%0,%1}, {%2,%3,%4,%5}, {%6,%7}, {%0,%1};" \
    : "+r"((D)[0]), "+r"((D)[1]) \
    : "r"((A)[0]), "r"((A)[1]), "r"((A)[2]), "r"((A)[3]), "r"(B0), "r"(B1))

__device__ __forceinline__ uint32_t swz(uint32_t base, int row, int col) {
    uint32_t off = (uint32_t)(row * 128 + col);
    return base + (off ^ ((off >> 3) & 0x70));
}

// ---------------- prep kernels ----------------
// transpose x[b][c][t] -> xT[b][t][c] fp16 hi/lo; tile 256 writes the 32-row pad
__global__ void __launch_bounds__(256) prep_x_k(const float* __restrict__ x) {
    __shared__ float xs[64][65];
    int b = blockIdx.y, tile = blockIdx.x, tid = threadIdx.x;
    if (tile == 256) {   // pad rows [TT, TP)
        for (int idx = tid; idx < 2048; idx += 256) {
            int t = idx >> 6, c = idx & 63;
            size_t off = ((size_t)b * TP + TT + t) * 64 + c;
            g_xh[off] = __float2half(0.f);
            g_xl[off] = __float2half(0.f);
        }
        return;
    }
    int t0 = tile * 64;
    for (int idx = tid; idx < 4096; idx += 256) {
        int c = idx >> 6, t = idx & 63;
        xs[c][t] = x[((size_t)b * 64 + c) * TT + t0 + t];
    }
    __syncthreads();
    for (int idx = tid; idx < 4096; idx += 256) {
        int t = idx >> 6, c = idx & 63;
        float v = xs[c][t];
        __half h = __float2half(v);
        __half l = __float2half(v - __half2float(h));
        size_t off = ((size_t)b * TP + t0 + t) * 64 + c;
        g_xh[off] = h;
        g_xl[off] = l;
    }
}

__global__ void prep_w_k(const float* __restrict__ w1, const float* __restrict__ w2) {
    int gid = blockIdx.x * blockDim.x + threadIdx.x;
    if (gid >= KW * 128 * 64) return;
    int k = gid >> 13, o = (gid >> 6) & 127, i = gid & 63;
    const float* w = (o >= 64) ? w2 : w1;
    g_wh[gid] = __float2half(w[((o & 63) * 64 + i) * KW + k]);
}

// ---------------- conv via mma.sync (fp16, x hi/lo; lo pass in f16-acc) ----------------
__global__ void __launch_bounds__(256, 2) conv_k(const int* __restrict__ orig_len) {
    extern __shared__ __align__(16) char sm[];
    const int tid = threadIdx.x, wid = tid >> 5, lane = tid & 31;
    const int tb = blockIdx.x, b = blockIdx.y;
    const int t0 = tb * 128;
    const uint32_t smb = smem_u32(sm);
    const int wm = wid >> 1;      /* t-group 0..3 (32 rows)  */
    const int wn = wid & 1;       /* o-half 0..1 (64 cols)   */

    // ---- prologue: async-stage A window (148 rows) + B taps {0,1} ----
    {
        const uint4* sH = (const uint4*)g_xh + ((size_t)b * TP + t0) * 8;
        const uint4* sL = (const uint4*)g_xl + ((size_t)b * TP + t0) * 8;
        for (int idx = tid; idx < 1184; idx += 256) {
            uint32_t off = (uint32_t)((idx >> 3) * 128 + (idx & 7) * 16);
            uint32_t d = off ^ ((off >> 3) & 0x70);
            cp16(smb + OFF_AH + d, sH + idx);
            cp16(smb + OFF_AL + d, sL + idx);
        }
        const uint4* wH = (const uint4*)g_wh;   // taps 0,1 contiguous
        for (int idx = tid; idx < 2048; idx += 256) {
            int i = idx & 1023;
            uint32_t off = (uint32_t)((i >> 3) * 128 + (i & 7) * 16);
            uint32_t d = off ^ ((off >> 3) & 0x70);
            cp16(smb + OFF_B + (idx >> 10) * 16384 + d, wH + idx);
        }
        CP_COMMIT;
    }

    float acc[2][8][4];
    uint32_t accL[2][8][2];
#pragma unroll
    for (int mt = 0; mt < 2; mt++)
#pragma unroll
        for (int nt = 0; nt < 8; nt++) {
#pragma unroll
            for (int e = 0; e < 4; e++) acc[mt][nt][e] = 0.f;
            accL[mt][nt][0] = 0u; accL[mt][nt][1] = 0u;
        }

#pragma unroll 1
    for (int jj = 0; jj < 11; jj++) {
        const int buf = jj & 1;
        if (jj < 10) {   // stage next tap pair into other buffer
            const int np = jj + 1;
            const int cnt = (np == 10) ? 1024 : 2048;   // last pair = tap 20 only
            const uint4* wH = (const uint4*)g_wh + (2 * np) * 1024;
            uint32_t db = smb + OFF_B + (buf ^ 1) * 32768;
            for (int idx = tid; idx < cnt; idx += 256) {
                int i = idx & 1023;
                uint32_t off = (uint32_t)((i >> 3) * 128 + (i & 7) * 16);
                uint32_t d = off ^ ((off >> 3) & 0x70);
                cp16(db + (idx >> 10) * 16384 + d, wH + idx);
            }
            CP_COMMIT;
            CP_WAIT1;
        } else {
            CP_WAIT0;
        }
        __syncthreads();

        const int ntap = (jj == 10) ? 1 : 2;
#pragma unroll 1
        for (int tt = 0; tt < ntap; tt++) {
            const int k = 2 * jj + tt;
            const uint32_t bBase = smb + OFF_B + buf * 32768 + tt * 16384;
#pragma unroll
            for (int ks = 0; ks < 4; ks++) {
                const int colA = ks * 32 + ((lane >> 4) << 4);
                uint32_t ah[2][4], al[2][4];
#pragma unroll
                for (int mt = 0; mt < 2; mt++) {
                    int row = wm * 32 + k + mt * 16 + (lane & 15);
                    ldsm4(ah[mt], swz(smb + OFF_AH, row, colA));
                    ldsm4(al[mt], swz(smb + OFF_AL, row, colA));
                }
#pragma unroll
                for (int g = 0; g < 4; g++) {
                    int row = wn * 64 + g * 16 + (lane & 15);
                    uint32_t r[4];
                    ldsm4(r, swz(bBase, row, colA));
                    // main pass (f32 acc)
                    MMA16816(acc[0][2 * g],     ah[0], r[0], r[2]);
                    MMA16816(acc[1][2 * g],     ah[1], r[0], r[2]);
                    MMA16816(acc[0][2 * g + 1], ah[0], r[1], r[3]);
                    MMA16816(acc[1][2 * g + 1], ah[1], r[1], r[3]);
                    // lo-correction pass (f16 acc)
                    MMAH16816(accL[0][2 * g],     al[0], r[0], r[2]);
                    MMAH16816(accL[1][2 * g],     al[1], r[0], r[2]);
                    MMAH16816(accL[0][2 * g + 1], al[0], r[1], r[3]);
                    MMAH16816(accL[1][2 * g + 1], al[1], r[1], r[3]);
                }
            }
        }
        __syncthreads();
    }

    // fold f16 correction into f32 accumulators
#pragma unroll
    for (int mt = 0; mt < 2; mt++)
#pragma unroll
        for (int nt = 0; nt < 8; nt++) {
            __half2 h0 = *(__half2*)&accL[mt][nt][0];
            __half2 h1 = *(__half2*)&accL[mt][nt][1];
            acc[mt][nt][0] += __half2float(h0.x);
            acc[mt][nt][1] += __half2float(h0.y);
            acc[mt][nt][2] += __half2float(h1.x);
            acc[mt][nt][3] += __half2float(h1.y);
        }

    // ---- epilogue: stage D[o][t] in smem (reuse A/B region) ----
    float* smD = (float*)sm;    // 128 x 132 floats = 67584 B
    {
        const int lo2 = 2 * (lane & 3), lt = lane >> 2;
#pragma unroll
        for (int mt = 0; mt < 2; mt++)
#pragma unroll
            for (int nt = 0; nt < 8; nt++) {
                int o = wn * 64 + nt * 8 + lo2;
                int t = wm * 32 + mt * 16 + lt;
                smD[o * 132 + t]           = acc[mt][nt][0];
                smD[(o + 1) * 132 + t]     = acc[mt][nt][1];
                smD[o * 132 + t + 8]       = acc[mt][nt][2];
                smD[(o + 1) * 132 + t + 8] = acc[mt][nt][3];
            }
    }
    __syncthreads();

    const int L = orig_len[b] - (KW - 1);
    const int strd = L >> 1, kern = L - strd;
    const int cta = b * 128 + tb;

#pragma unroll 1
    for (int oi = 0; oi < 16; oi++) {
        const int o = wid * 16 + oi;
        float4 v = *(const float4*)(smD + o * 132 + lane * 4);
        float vv[4] = {v.x, v.y, v.z, v.w};
        float s = 0.f, q = 0.f;
        float m0 = -FLT_MAX, m1 = -FLT_MAX, m2 = -FLT_MAX;
        const int tg0 = t0 + lane * 4;
#pragma unroll
        for (int e = 0; e < 4; e++) {
            int tg = tg0 + e;
            float xv = vv[e];
            if (tg < TCV) { s += xv; q += xv * xv; }
            if (o < 64) {
                if (tg < L) { m0 = fmaxf(m0, xv); if (tg >= strd) m2 = fmaxf(m2, xv); }
                if (tg < kern) m1 = fmaxf(m1, xv);
            }
        }
        if (o >= 64)   // conv2 raw output needed elementwise for avg-pool(leaky)
            *(float4*)(g_y2 + ((size_t)(b * 64 + (o - 64))) * TT + t0 + lane * 4) = v;
#pragma unroll
        for (int off = 16; off; off >>= 1) {
            s += __shfl_xor_sync(0xffffffffu, s, off);
            q += __shfl_xor_sync(0xffffffffu, q, off);
            m0 = fmaxf(m0, __shfl_xor_sync(0xffffffffu, m0, off));
            m1 = fmaxf(m1, __shfl_xor_sync(0xffffffffu, m1, off));
            m2 = fmaxf(m2, __shfl_xor_sync(0xffffffffu, m2, off));
        }
        if (lane == 0) {
            g_bs[o * 4096 + cta] = s;
            g_bs[(128 + o) * 4096 + cta] = q;
            if (o < 64) {
                float* p = g_part + ((b * 64 + o) * 3) * 128 + tb;
                p[0] = m0; p[128] = m1; p[256] = m2;
            }
        }
    }
}

// ---------------- BN stats reduce ----------------
__global__ void __launch_bounds__(256) stats_k() {
    __shared__ double sd[256];
    int slot = blockIdx.x, tid = threadIdx.x;
    double a = 0.0;
    for (int i = tid; i < 4096; i += 256) a += (double)g_bs[(size_t)slot * 4096 + i];
    sd[tid] = a;
    __syncthreads();
    for (int s = 128; s; s >>= 1) { if (tid < s) sd[tid] += sd[tid + s]; __syncthreads(); }
    if (tid == 0) {
        if (slot < 128) g_sumd[slot] = sd[0];
        else g_sqd[slot - 128] = sd[0];
    }
}

// ---------------- max-branch features (conv1) ----------------
__global__ void featmax_k(const float* __restrict__ g1, const float* __restrict__ b1) {
    int b = blockIdx.x, j = threadIdx.x;   // 192 threads
    if (j >= 192) return;
    int o, w;
    if (j < 64) { o = j; w = 0; } else { o = (j - 64) >> 1; w = 1 + ((j - 64) & 1); }
    const float* p = g_part + ((b * 64 + o) * 3 + w) * 128;
    float m = -FLT_MAX;
    for (int t = 0; t < 128; t++) m = fmaxf(m, p[t]);
    const double CNT = (double)BB * (double)TCV;
    double mu = g_sumd[o] / CNT;
    double va = g_sqd[o] / CNT - mu * mu;
    double scd = (double)g1[o] / sqrt(va + 1e-5);
    float z = (float)(scd * (double)m + ((double)b1[o] - mu * scd));
    z = (z > 0.f) ? z : 0.01f * z;
    g_feat[b * 384 + j] = z;
}

// ---------------- avg-branch (conv2): BN + leaky + windowed sums ----------------
__global__ void __launch_bounds__(256) pool2_k(const int* __restrict__ orig_len,
                                               const float* __restrict__ g2, const float* __restrict__ b2) {
    const int c = blockIdx.x, b = blockIdx.y;
    const int tid = threadIdx.x;
    const int L = orig_len[b] - (KW - 1);
    const int strd = L >> 1, kern = L - strd;

    const double CNT = (double)BB * (double)TCV;
    double mu = g_sumd[64 + c] / CNT;
    double va = g_sqd[64 + c] / CNT - mu * mu;
    double scd = (double)g2[c] / sqrt(va + 1e-5);
    const float sc = (float)scd;
    const float sh = (float)((double)b2[c] - mu * scd);

    const float* yr = g_y2 + ((size_t)b * 64 + c) * TT;
    float s0 = 0.f, s1 = 0.f, s2 = 0.f;
    for (int t = tid; t < L; t += 256) {
        float z = sc * yr[t] + sh;
        z = (z > 0.f) ? z : 0.01f * z;
        s0 += z;
        if (t < kern) s1 += z;
        if (t >= strd) s2 += z;
    }
#pragma unroll
    for (int off = 16; off; off >>= 1) {
        s0 += __shfl_down_sync(0xffffffffu, s0, off);
        s1 += __shfl_down_sync(0xffffffffu, s1, off);
        s2 += __shfl_down_sync(0xffffffffu, s2, off);
    }
    __shared__ float red[8][3];
    if ((tid & 31) == 0) { int w = tid >> 5; red[w][0] = s0; red[w][1] = s1; red[w][2] = s2; }
    __syncthreads();
    if (tid == 0) {
        float t0v = 0.f, t1v = 0.f, t2v = 0.f;
#pragma unroll
        for (int w = 0; w < 8; w++) { t0v += red[w][0]; t1v += red[w][1]; t2v += red[w][2]; }
        float* f = g_feat + b * 384;
        f[192 + c] = t0v / (float)L;
        f[256 + 2 * c]     = t1v / (float)kern;
        f[256 + 2 * c + 1] = t2v / (float)kern;
    }
}

// ---------------- FC head ----------------
__global__ void fc_k(const float* __restrict__ fc_w, const float* __restrict__ fc_b,
                     float* __restrict__ out) {
    int tid = threadIdx.x;
    if (tid >= BB * 2) return;
    int b = tid >> 1, task = tid & 1;
    const float* f = g_feat + b * 384;
    const float* w = fc_w + task * 384;
    float acc = fc_b[task];
#pragma unroll 8
    for (int j = 0; j < 384; j++) acc += f[j] * w[j];
    out[b * 2 + task] = acc;
}

// ---------------- launch ----------------
extern "C" void kernel_launch(void* const* d_in, const int* in_sizes, int n_in,
                              void* d_out, int out_size) {
    const float* x        = (const float*)d_in[0];
    const int*   orig_len = (const int*)d_in[1];
    const float* w1   = (const float*)d_in[2];
    const float* g1   = (const float*)d_in[3];
    const float* b1   = (const float*)d_in[4];
    const float* w2   = (const float*)d_in[5];
    const float* g2   = (const float*)d_in[6];
    const float* b2   = (const float*)d_in[7];
    const float* fc_w = (const float*)d_in[8];
    const float* fc_b = (const float*)d_in[9];
    float* out = (float*)d_out;

    cudaFuncSetAttribute(conv_k, cudaFuncAttributeMaxDynamicSharedMemorySize, SMEM_TOTAL);

    dim3 xg(257, BB);
    prep_x_k<<<xg, 256>>>(x);
    prep_w_k<<<(KW * 128 * 64 + 255) / 256, 256>>>(w1, w2);

    dim3 cg(128, BB);
    conv_k<<<cg, 256, SMEM_TOTAL>>>(orig_len);

    stats_k<<<256, 256>>>();
    featmax_k<<<BB, 192>>>(g1, b1);
    dim3 pg(64, BB);
    pool2_k<<<pg, 256>>>(orig_len, g2, b2);

    fc_k<<<1, 64>>>(fc_w, fc_b, out);
}

// round 15
// speedup vs baseline: 1.7364x; 1.7364x over previous
#include <cuda_runtime.h>
#include <cuda_fp16.h>
#include <cstdint>
#include <cfloat>

#define BB 32
#define TT 16384
#define TP 16416
#define KW 21
#define TCV (TT - KW + 1)   /* 16364 */

// smem: A[148x128B] | B[2 bufs][16K]; epilogue reuses as smD (128x132 f32)
#define OFF_A  0
#define OFF_B  18944
#define SMEM_TOTAL 67584

// ---------------- device scratch ----------------
__device__ __align__(16) __half g_xh[BB * TP * 64];
__device__ __align__(16) __half g_wh[KW * 128 * 64];
__device__ __align__(16) float g_y2[(size_t)BB * 64 * TT];   /* conv2 raw [b][c][t] */
__device__ float g_bs[256 * 4096];                           /* stats partials [slot][cta] */
__device__ float g_part[32 * 64 * 3 * 128];                  /* max partials [b][c][w][tile] */
__device__ double g_sumd[128];
__device__ double g_sqd[128];
__device__ float g_feat[BB * 384];

// ---------------- asm helpers (sm_80-portable) ----------------
__device__ __forceinline__ uint32_t smem_u32(const void* p) {
    uint32_t r;
    asm("{ .reg .u64 t; cvta.to.shared.u64 t, %1; cvt.u32.u64 %0, t; }" : "=r"(r) : "l"(p));
    return r;
}
__device__ __forceinline__ void cp16(uint32_t d, const void* s) {
    asm volatile("cp.async.cg.shared.global [%0], [%1], 16;" :: "r"(d), "l"(s));
}
#define CP_COMMIT asm volatile("cp.async.commit_group;" ::: "memory")
#define CP_WAIT1  asm volatile("cp.async.wait_group 1;" ::: "memory")
#define CP_WAIT0  asm volatile("cp.async.wait_group 0;" ::: "memory")

__device__ __forceinline__ void ldsm4(uint32_t* r, uint32_t a) {
    asm volatile("ldmatrix.sync.aligned.m8n8.x4.shared.b16 {%0,%1,%2,%3}, [%4];"
        : "=r"(r[0]), "=r"(r[1]), "=r"(r[2]), "=r"(r[3]) : "r"(a));
}
#define MMA16816(D, A, B0, B1) asm volatile( \
    "mma.sync.aligned.m16n8k16.row.col.f32.f16.f16.f32 " \
    "{%0,%1,%2,%3}, {%4,%5,%6,%7}, {%8,%9}, {%0,%1,%2,%3};" \
    : "+f"((D)[0]), "+f"((D)[1]), "+f"((D)[2]), "+f"((D)[3]) \
    : "r"((A)[0]), "r"((A)[1]), "r"((A)[2]), "r"((A)[3]), "r"(B0), "r"(B1))

__device__ __forceinline__ uint32_t swz(uint32_t base, int row, int col) {
    uint32_t off = (uint32_t)(row * 128 + col);
    return base + (off ^ ((off >> 3) & 0x70));
}

// ---------------- prep kernels ----------------
// transpose x[b][c][t] -> xT[b][t][c] fp16; tile 256 writes the 32-row pad
__global__ void __launch_bounds__(256) prep_x_k(const float* __restrict__ x) {
    __shared__ float xs[64][65];
    int b = blockIdx.y, tile = blockIdx.x, tid = threadIdx.x;
    if (tile == 256) {   // pad rows [TT, TP)
        for (int idx = tid; idx < 2048; idx += 256) {
            int t = idx >> 6, c = idx & 63;
            g_xh[((size_t)b * TP + TT + t) * 64 + c] = __float2half(0.f);
        }
        return;
    }
    int t0 = tile * 64;
    for (int idx = tid; idx < 4096; idx += 256) {
        int c = idx >> 6, t = idx & 63;
        xs[c][t] = x[((size_t)b * 64 + c) * TT + t0 + t];
    }
    __syncthreads();
    for (int idx = tid; idx < 4096; idx += 256) {
        int t = idx >> 6, c = idx & 63;
        g_xh[((size_t)b * TP + t0 + t) * 64 + c] = __float2half(xs[c][t]);
    }
}

__global__ void prep_w_k(const float* __restrict__ w1, const float* __restrict__ w2) {
    int gid = blockIdx.x * blockDim.x + threadIdx.x;
    if (gid >= KW * 128 * 64) return;
    int k = gid >> 13, o = (gid >> 6) & 127, i = gid & 63;
    const float* w = (o >= 64) ? w2 : w1;
    g_wh[gid] = __float2half(w[((o & 63) * 64 + i) * KW + k]);
}

// ---------------- conv via mma.sync (single-pass fp16) ----------------
__global__ void __launch_bounds__(256, 2) conv_k(const int* __restrict__ orig_len) {
    extern __shared__ __align__(16) char sm[];
    const int tid = threadIdx.x, wid = tid >> 5, lane = tid & 31;
    const int tb = blockIdx.x, b = blockIdx.y;
    const int t0 = tb * 128;
    const uint32_t smb = smem_u32(sm);
    const int wm = wid >> 1;      /* t-group 0..3 (32 rows)  */
    const int wn = wid & 1;       /* o-half 0..1 (64 cols)   */

    // ---- prologue: async-stage A window (148 rows) + B tap 0 ----
    {
        const uint4* sH = (const uint4*)g_xh + ((size_t)b * TP + t0) * 8;
        for (int idx = tid; idx < 1184; idx += 256) {
            uint32_t off = (uint32_t)((idx >> 3) * 128 + (idx & 7) * 16);
            uint32_t d = off ^ ((off >> 3) & 0x70);
            cp16(smb + OFF_A + d, sH + idx);
        }
        const uint4* wH = (const uint4*)g_wh;
        for (int idx = tid; idx < 1024; idx += 256) {
            uint32_t off = (uint32_t)((idx >> 3) * 128 + (idx & 7) * 16);
            uint32_t d = off ^ ((off >> 3) & 0x70);
            cp16(smb + OFF_B + d, wH + idx);
        }
        CP_COMMIT;
    }

    float acc[2][8][4];
#pragma unroll
    for (int mt = 0; mt < 2; mt++)
#pragma unroll
        for (int nt = 0; nt < 8; nt++)
#pragma unroll
            for (int e = 0; e < 4; e++) acc[mt][nt][e] = 0.f;

#pragma unroll 1
    for (int k = 0; k < 21; k++) {
        const int buf = k & 1;
        if (k < 20) {   // stage next tap into other buffer
            const uint4* wH = (const uint4*)g_wh + (k + 1) * 1024;
            uint32_t db = smb + OFF_B + (buf ^ 1) * 16384;
            for (int idx = tid; idx < 1024; idx += 256) {
                uint32_t off = (uint32_t)((idx >> 3) * 128 + (idx & 7) * 16);
                uint32_t d = off ^ ((off >> 3) & 0x70);
                cp16(db + d, wH + idx);
            }
            CP_COMMIT;
            CP_WAIT1;
        } else {
            CP_WAIT0;
        }
        __syncthreads();

        const uint32_t bBase = smb + OFF_B + buf * 16384;
#pragma unroll
        for (int ks = 0; ks < 4; ks++) {
            const int colA = ks * 32 + ((lane >> 4) << 4);
            uint32_t ah[2][4];
#pragma unroll
            for (int mt = 0; mt < 2; mt++) {
                int row = wm * 32 + k + mt * 16 + (lane & 15);
                ldsm4(ah[mt], swz(smb + OFF_A, row, colA));
            }
#pragma unroll
            for (int g = 0; g < 4; g++) {
                int row = wn * 64 + g * 16 + (lane & 15);
                uint32_t r[4];
                ldsm4(r, swz(bBase, row, colA));
                MMA16816(acc[0][2 * g],     ah[0], r[0], r[2]);
                MMA16816(acc[1][2 * g],     ah[1], r[0], r[2]);
                MMA16816(acc[0][2 * g + 1], ah[0], r[1], r[3]);
                MMA16816(acc[1][2 * g + 1], ah[1], r[1], r[3]);
            }
        }
        __syncthreads();
    }

    // ---- epilogue: stage D[o][t] in smem (reuse A/B region) ----
    float* smD = (float*)sm;    // 128 x 132 floats = 67584 B
    {
        const int lo2 = 2 * (lane & 3), lt = lane >> 2;
#pragma unroll
        for (int mt = 0; mt < 2; mt++)
#pragma unroll
            for (int nt = 0; nt < 8; nt++) {
                int o = wn * 64 + nt * 8 + lo2;
                int t = wm * 32 + mt * 16 + lt;
                smD[o * 132 + t]           = acc[mt][nt][0];
                smD[(o + 1) * 132 + t]     = acc[mt][nt][1];
                smD[o * 132 + t + 8]       = acc[mt][nt][2];
                smD[(o + 1) * 132 + t + 8] = acc[mt][nt][3];
            }
    }
    __syncthreads();

    const int L = orig_len[b] - (KW - 1);
    const int strd = L >> 1, kern = L - strd;
    const int cta = b * 128 + tb;

#pragma unroll 1
    for (int oi = 0; oi < 16; oi++) {
        const int o = wid * 16 + oi;
        float4 v = *(const float4*)(smD + o * 132 + lane * 4);
        float vv[4] = {v.x, v.y, v.z, v.w};
        float s = 0.f, q = 0.f;
        float m0 = -FLT_MAX, m1 = -FLT_MAX, m2 = -FLT_MAX;
        const int tg0 = t0 + lane * 4;
#pragma unroll
        for (int e = 0; e < 4; e++) {
            int tg = tg0 + e;
            float xv = vv[e];
            if (tg < TCV) { s += xv; q += xv * xv; }
            if (o < 64) {
                if (tg < L) { m0 = fmaxf(m0, xv); if (tg >= strd) m2 = fmaxf(m2, xv); }
                if (tg < kern) m1 = fmaxf(m1, xv);
            }
        }
        if (o >= 64)   // conv2 raw output needed elementwise for avg-pool(leaky)
            *(float4*)(g_y2 + ((size_t)(b * 64 + (o - 64))) * TT + t0 + lane * 4) = v;
#pragma unroll
        for (int off = 16; off; off >>= 1) {
            s += __shfl_xor_sync(0xffffffffu, s, off);
            q += __shfl_xor_sync(0xffffffffu, q, off);
            m0 = fmaxf(m0, __shfl_xor_sync(0xffffffffu, m0, off));
            m1 = fmaxf(m1, __shfl_xor_sync(0xffffffffu, m1, off));
            m2 = fmaxf(m2, __shfl_xor_sync(0xffffffffu, m2, off));
        }
        if (lane == 0) {
            g_bs[o * 4096 + cta] = s;
            g_bs[(128 + o) * 4096 + cta] = q;
            if (o < 64) {
                float* p = g_part + ((b * 64 + o) * 3) * 128 + tb;
                p[0] = m0; p[128] = m1; p[256] = m2;
            }
        }
    }
}

// ---------------- BN stats reduce ----------------
__global__ void __launch_bounds__(256) stats_k() {
    __shared__ double sd[256];
    int slot = blockIdx.x, tid = threadIdx.x;
    double a = 0.0;
    for (int i = tid; i < 4096; i += 256) a += (double)g_bs[(size_t)slot * 4096 + i];
    sd[tid] = a;
    __syncthreads();
    for (int s = 128; s; s >>= 1) { if (tid < s) sd[tid] += sd[tid + s]; __syncthreads(); }
    if (tid == 0) {
        if (slot < 128) g_sumd[slot] = sd[0];
        else g_sqd[slot - 128] = sd[0];
    }
}

// ---------------- max-branch features (conv1) ----------------
__global__ void featmax_k(const float* __restrict__ g1, const float* __restrict__ b1) {
    int b = blockIdx.x, j = threadIdx.x;   // 192 threads
    if (j >= 192) return;
    int o, w;
    if (j < 64) { o = j; w = 0; } else { o = (j - 64) >> 1; w = 1 + ((j - 64) & 1); }
    const float* p = g_part + ((b * 64 + o) * 3 + w) * 128;
    float m = -FLT_MAX;
    for (int t = 0; t < 128; t++) m = fmaxf(m, p[t]);
    const double CNT = (double)BB * (double)TCV;
    double mu = g_sumd[o] / CNT;
    double va = g_sqd[o] / CNT - mu * mu;
    double scd = (double)g1[o] / sqrt(va + 1e-5);
    float z = (float)(scd * (double)m + ((double)b1[o] - mu * scd));
    z = (z > 0.f) ? z : 0.01f * z;
    g_feat[b * 384 + j] = z;
}

// ---------------- avg-branch (conv2): BN + leaky + windowed sums ----------------
__global__ void __launch_bounds__(256) pool2_k(const int* __restrict__ orig_len,
                                               const float* __restrict__ g2, const float* __restrict__ b2) {
    const int c = blockIdx.x, b = blockIdx.y;
    const int tid = threadIdx.x;
    const int L = orig_len[b] - (KW - 1);
    const int strd = L >> 1, kern = L - strd;

    const double CNT = (double)BB * (double)TCV;
    double mu = g_sumd[64 + c] / CNT;
    double va = g_sqd[64 + c] / CNT - mu * mu;
    double scd = (double)g2[c] / sqrt(va + 1e-5);
    const float sc = (float)scd;
    const float sh = (float)((double)b2[c] - mu * scd);

    const float* yr = g_y2 + ((size_t)b * 64 + c) * TT;
    float s0 = 0.f, s1 = 0.f, s2 = 0.f;
    for (int t = tid; t < L; t += 256) {
        float z = sc * yr[t] + sh;
        z = (z > 0.f) ? z : 0.01f * z;
        s0 += z;
        if (t < kern) s1 += z;
        if (t >= strd) s2 += z;
    }
#pragma unroll
    for (int off = 16; off; off >>= 1) {
        s0 += __shfl_down_sync(0xffffffffu, s0, off);
        s1 += __shfl_down_sync(0xffffffffu, s1, off);
        s2 += __shfl_down_sync(0xffffffffu, s2, off);
    }
    __shared__ float red[8][3];
    if ((tid & 31) == 0) { int w = tid >> 5; red[w][0] = s0; red[w][1] = s1; red[w][2] = s2; }
    __syncthreads();
    if (tid == 0) {
        float t0v = 0.f, t1v = 0.f, t2v = 0.f;
#pragma unroll
        for (int w = 0; w < 8; w++) { t0v += red[w][0]; t1v += red[w][1]; t2v += red[w][2]; }
        float* f = g_feat + b * 384;
        f[192 + c] = t0v / (float)L;
        f[256 + 2 * c]     = t1v / (float)kern;
        f[256 + 2 * c + 1] = t2v / (float)kern;
    }
}

// ---------------- FC head ----------------
__global__ void fc_k(const float* __restrict__ fc_w, const float* __restrict__ fc_b,
                     float* __restrict__ out) {
    int tid = threadIdx.x;
    if (tid >= BB * 2) return;
    int b = tid >> 1, task = tid & 1;
    const float* f = g_feat + b * 384;
    const float* w = fc_w + task * 384;
    float acc = fc_b[task];
#pragma unroll 8
    for (int j = 0; j < 384; j++) acc += f[j] * w[j];
    out[b * 2 + task] = acc;
}

// ---------------- launch ----------------
extern "C" void kernel_launch(void* const* d_in, const int* in_sizes, int n_in,
                              void* d_out, int out_size) {
    const float* x        = (const float*)d_in[0];
    const int*   orig_len = (const int*)d_in[1];
    const float* w1   = (const float*)d_in[2];
    const float* g1   = (const float*)d_in[3];
    const float* b1   = (const float*)d_in[4];
    const float* w2   = (const float*)d_in[5];
    const float* g2   = (const float*)d_in[6];
    const float* b2   = (const float*)d_in[7];
    const float* fc_w = (const float*)d_in[8];
    const float* fc_b = (const float*)d_in[9];
    float* out = (float*)d_out;

    cudaFuncSetAttribute(conv_k, cudaFuncAttributeMaxDynamicSharedMemorySize, SMEM_TOTAL);

    dim3 xg(257, BB);
    prep_x_k<<<xg, 256>>>(x);
    prep_w_k<<<(KW * 128 * 64 + 255) / 256, 256>>>(w1, w2);

    dim3 cg(128, BB);
    conv_k<<<cg, 256, SMEM_TOTAL>>>(orig_len);

    stats_k<<<256, 256>>>();
    featmax_k<<<BB, 192>>>(g1, b1);
    dim3 pg(64, BB);
    pool2_k<<<pg, 256>>>(orig_len, g2, b2);

    fc_k<<<1, 64>>>(fc_w, fc_b, out);
}